// round 12
// baseline (speedup 1.0000x reference)
#include <cuda_runtime.h>
#include <cstdint>

#define BATCH 32
#define NPTS  65536
#define SSAMP 512
#define CPB   8                 // CTAs per cluster (= per batch)
#define PSH   (NPTS / CPB)      // 8192 points per CTA shard per batch
#define TPB   512
#define NWARP (TPB / 32)        // 16 warps
#define NSLOT (CPB * NWARP)     // 128 candidate slots per batch per parity
#define PAIRS (PSH / (2 * TPB)) // 8 point-pairs per thread per batch
#define PPT   (2 * PAIRS)       // 16 points per thread per batch

__device__ int g_idx[BATCH][SSAMP];

#define ADD_F32X2(out, a, b) \
    asm("add.rn.f32x2 %0, %1, %2;" : "=l"(out) : "l"(a), "l"(b))
#define MUL_F32X2(out, a, b) \
    asm("mul.rn.f32x2 %0, %1, %2;" : "=l"(out) : "l"(a), "l"(b))
#define FMA_F32X2(out, a, b, c) \
    asm("fma.rn.f32x2 %0, %1, %2, %3;" : "=l"(out) : "l"(a), "l"(b), "l"(c))
#define PACK_F32X2(out, lo, hi) \
    asm("mov.b64 %0, {%1, %2};" : "=l"(out) : "r"(lo), "r"(hi))
#define UNPACK_F32X2(lo, hi, in) \
    asm("mov.b64 {%0, %1}, %2;" : "=r"(lo), "=r"(hi) : "l"(in))
#define REDUX_MAX_U32(out, in) \
    asm("redux.sync.max.u32 %0, %1, 0xffffffff;" : "=r"(out) : "r"(in))

// Scan one batch's shard, compute warp candidate, push to all 8 cluster
// ranks via DSMEM, arrive on their mbarrier. Pure latency goes off-path:
// the caller interleaves the OTHER batch between send and wait.
__device__ __forceinline__ void scan_send(
    const ulonglong2* __restrict__ xyp,
    const unsigned long long* __restrict__ zs2,
    const float* __restrict__ xyf, const float* __restrict__ zsf,
    float* dist, float cx, float cy, float cz,
    int t, int lane, int slot, int base,
    uint32_t kaddr_l, uint32_t caddr_l, uint32_t mb_l)
{
    unsigned long long ncx2, ncy2, ncz2;
    {
        uint32_t nx = __float_as_uint(-cx);
        uint32_t ny = __float_as_uint(-cy);
        uint32_t nz = __float_as_uint(-cz);
        PACK_F32X2(ncx2, nx, nx);
        PACK_F32X2(ncy2, ny, ny);
        PACK_F32X2(ncz2, nz, nz);
    }
    float b0 = -1.0f, b1 = -1.0f, b2 = -1.0f, b3 = -1.0f;
#pragma unroll
    for (int jj = 0; jj < PAIRS; jj++) {
        int q = t + jj * TPB;
        ulonglong2 xy = xyp[q];              // LDS.128
        unsigned long long z2 = zs2[q];      // LDS.64
        unsigned long long dx2, dy2, dz2, s2;
        ADD_F32X2(dx2, xy.x, ncx2);
        ADD_F32X2(dy2, xy.y, ncy2);
        ADD_F32X2(dz2, z2,   ncz2);
        MUL_F32X2(s2, dx2, dx2);
        FMA_F32X2(s2, dy2, dy2, s2);
        FMA_F32X2(s2, dz2, dz2, s2);
        uint32_t lo, hi;
        UNPACK_F32X2(lo, hi, s2);
        float v0 = fminf(dist[2 * jj],     __uint_as_float(lo));
        float v1 = fminf(dist[2 * jj + 1], __uint_as_float(hi));
        dist[2 * jj]     = v0;
        dist[2 * jj + 1] = v1;
        if (jj & 1) { b2 = fmaxf(b2, v0); b3 = fmaxf(b3, v1); }
        else        { b0 = fmaxf(b0, v0); b1 = fmaxf(b1, v1); }
    }
    float bv = fmaxf(fmaxf(b0, b1), fmaxf(b2, b3));

    int bp = 0;
#pragma unroll
    for (int k = PPT - 1; k >= 0; k--) {
        int p = 2 * (t + (k >> 1) * TPB) + (k & 1);
        if (dist[k] == bv) bp = p;
    }

    unsigned khi = __float_as_uint(bv);
    unsigned klo = ~(unsigned)(base + bp);
    unsigned H, L;
    REDUX_MAX_U32(H, khi);
    unsigned cand = (khi == H) ? klo : 0u;
    REDUX_MAX_U32(L, cand);
    unsigned long long wkey = ((unsigned long long)H << 32) | L;

    int off = (int)(~L) - base;
    if (lane < CPB) {
        float wx = xyf[(off >> 1) * 4 + (off & 1)];
        float wy = xyf[(off >> 1) * 4 + 2 + (off & 1)];
        float wz = zsf[off];
        uint32_t rk, rc, rm;
        asm("mapa.shared::cluster.u32 %0, %1, %2;" : "=r"(rk) : "r"(kaddr_l), "r"(lane));
        asm("mapa.shared::cluster.u32 %0, %1, %2;" : "=r"(rc) : "r"(caddr_l), "r"(lane));
        asm("mapa.shared::cluster.u32 %0, %1, %2;" : "=r"(rm) : "r"(mb_l),    "r"(lane));
        unsigned long long xy;
        PACK_F32X2(xy, __float_as_uint(wx), __float_as_uint(wy));
        asm volatile("st.shared::cluster.u64 [%0], %1;" :: "r"(rk), "l"(wkey) : "memory");
        asm volatile("st.shared::cluster.u64 [%0], %1;" :: "r"(rc), "l"(xy) : "memory");
        asm volatile("st.shared::cluster.u32 [%0+8], %1;" :: "r"(rc), "r"(__float_as_uint(wz)) : "memory");
        asm volatile("mbarrier.arrive.release.cluster.shared::cluster.b64 _, [%0];"
                     :: "r"(rm) : "memory");
    }
}

// Wait local parity mbarrier, reduce 128 candidates, return centroid + idx.
__device__ __forceinline__ void wait_reduce(
    uint32_t mb_l, unsigned ph,
    const unsigned long long* __restrict__ keys,
    const float4* __restrict__ coord,
    int lane, float& cx, float& cy, float& cz, int& widx)
{
    uint32_t done;
    do {
        asm volatile(
            "{\n\t.reg .pred p;\n\t"
            "mbarrier.try_wait.parity.acquire.cluster.shared::cta.b64 p, [%1], %2;\n\t"
            "selp.b32 %0, 1, 0, p;\n\t}"
            : "=r"(done) : "r"(mb_l), "r"(ph) : "memory");
    } while (!done);

    const ulonglong2* kk2 = (const ulonglong2*)keys;
    ulonglong2 ka = kk2[2 * lane];
    ulonglong2 kb = kk2[2 * lane + 1];
    unsigned long long km = ka.x; int si = 4 * lane;
    if (ka.y > km) { km = ka.y; si = 4 * lane + 1; }
    if (kb.x > km) { km = kb.x; si = 4 * lane + 2; }
    if (kb.y > km) { km = kb.y; si = 4 * lane + 3; }
    unsigned hi = (unsigned)(km >> 32), lo = (unsigned)km;
    unsigned Hg, Lg;
    REDUX_MAX_U32(Hg, hi);
    unsigned cnd = (hi == Hg) ? lo : 0u;
    REDUX_MAX_U32(Lg, cnd);
    unsigned long long W = ((unsigned long long)Hg << 32) | Lg;
    unsigned bal = __ballot_sync(0xffffffffu, km == W);
    int src = __ffs(bal) - 1;
    int sidx = __shfl_sync(0xffffffffu, si, src);
    float4 cc = coord[sidx];
    cx = cc.x; cy = cc.y; cz = cc.z;
    widx = (int)(~Lg);
}

// 16 clusters x 8 CTAs; each cluster runs TWO independent batches pipelined:
// batch B's scan fills batch A's exchange latency and vice versa.
__global__ void __launch_bounds__(TPB, 1) __cluster_dims__(CPB, 1, 1)
fps_kernel(const float* __restrict__ xyz) {
    extern __shared__ char smem_raw[];
    ulonglong2* xypA = (ulonglong2*)smem_raw;                    // 64KB
    ulonglong2* xypB = xypA + PSH / 2;                           // 64KB
    float* zsA = (float*)(xypB + PSH / 2);                       // 32KB
    float* zsB = zsA + PSH;                                      // 32KB
    unsigned long long* keys = (unsigned long long*)(zsB + PSH); // [2][2][128]
    float4* coord = (float4*)(keys + 4 * NSLOT);                 // [2][2][128]
    unsigned long long* mbar = (unsigned long long*)(coord + 4 * NSLOT); // [4]

    const int cta  = blockIdx.x;
    const int pr   = cta >> 3;          // batch pair 0..15
    const int c    = cta & 7;           // rank in cluster
    const int bA   = 2 * pr, bB = bA + 1;
    const int base = c * PSH;
    const int t    = threadIdx.x;
    const int w    = t >> 5;
    const int lane = t & 31;
    const float* XA = xyz + (size_t)bA * NPTS * 3;
    const float* XB = xyz + (size_t)bB * NPTS * 3;

    // Load both shards, deinterleave -> {xy-pairs, z}.
    float* xyfA = (float*)xypA;
    float* xyfB = (float*)xypB;
    for (int i = t; i < 3 * PSH; i += TPB) {
        int p = i / 3;
        int k = i - 3 * p;
        float vA = XA[(size_t)base * 3 + i];
        float vB = XB[(size_t)base * 3 + i];
        if (k == 2) { zsA[p] = vA; zsB[p] = vB; }
        else {
            int o = (p >> 1) * 4 + k * 2 + (p & 1);
            xyfA[o] = vA; xyfB[o] = vB;
        }
    }

    uint32_t keys_base  = (uint32_t)__cvta_generic_to_shared(keys);
    uint32_t coord_base = (uint32_t)__cvta_generic_to_shared(coord);
    uint32_t mbar_base  = (uint32_t)__cvta_generic_to_shared(mbar);
    if (t == 0) {
#pragma unroll
        for (int m = 0; m < 4; m++)
            asm volatile("mbarrier.init.shared.b64 [%0], %1;"
                         :: "r"(mbar_base + 8u * m), "r"((unsigned)NSLOT) : "memory");
    }
    __syncthreads();
    asm volatile("barrier.cluster.arrive.aligned;" ::: "memory");
    asm volatile("barrier.cluster.wait.aligned;" ::: "memory");

    const unsigned long long* zsA2 = (const unsigned long long*)zsA;
    const unsigned long long* zsB2 = (const unsigned long long*)zsB;

    float distA[PPT], distB[PPT];
#pragma unroll
    for (int j = 0; j < PPT; j++) { distA[j] = 1e10f; distB[j] = 1e10f; }

    float cxA = XA[0], cyA = XA[1], czA = XA[2];
    float cxB = XB[0], cyB = XB[1], czB = XB[2];
    if (c == 0 && t == 0) { g_idx[bA][0] = 0; g_idx[bB][0] = 0; }

    const int slot = c * NWARP + w;

    // slot addresses: index (g*2 + par)
#define KADDR(g, par) (keys_base  + ((uint32_t)((g) * 2 + (par)) * NSLOT + slot) * 8u)
#define CADDR(g, par) (coord_base + ((uint32_t)((g) * 2 + (par)) * NSLOT + slot) * 16u)
#define MB(g, par)    (mbar_base  + (uint32_t)((g) * 2 + (par)) * 8u)

    // iteration 0 sends (par=0)
    scan_send(xypA, zsA2, xyfA, zsA, distA, cxA, cyA, czA,
              t, lane, slot, base, KADDR(0, 0), CADDR(0, 0), MB(0, 0));
    scan_send(xypB, zsB2, xyfB, zsB, distB, cxB, cyB, czB,
              t, lane, slot, base, KADDR(1, 0), CADDR(1, 0), MB(1, 0));

    for (int i = 0; i < SSAMP - 2; i++) {
        const int par  = i & 1;
        const int parn = (i + 1) & 1;
        const unsigned ph = (unsigned)((i >> 1) & 1);
        int widx;
        wait_reduce(MB(0, par), ph, keys + (0 * 2 + par) * NSLOT,
                    coord + (0 * 2 + par) * NSLOT, lane, cxA, cyA, czA, widx);
        if (c == 0 && t == 0) g_idx[bA][i + 1] = widx;
        scan_send(xypA, zsA2, xyfA, zsA, distA, cxA, cyA, czA,
                  t, lane, slot, base, KADDR(0, parn), CADDR(0, parn), MB(0, parn));

        wait_reduce(MB(1, par), ph, keys + (1 * 2 + par) * NSLOT,
                    coord + (1 * 2 + par) * NSLOT, lane, cxB, cyB, czB, widx);
        if (c == 0 && t == 0) g_idx[bB][i + 1] = widx;
        scan_send(xypB, zsB2, xyfB, zsB, distB, cxB, cyB, czB,
                  t, lane, slot, base, KADDR(1, parn), CADDR(1, parn), MB(1, parn));
    }
    // final waits (iter SSAMP-2 = 510)
    {
        const int i = SSAMP - 2;
        const int par = i & 1;
        const unsigned ph = (unsigned)((i >> 1) & 1);
        int widx;
        wait_reduce(MB(0, par), ph, keys + (0 * 2 + par) * NSLOT,
                    coord + (0 * 2 + par) * NSLOT, lane, cxA, cyA, czA, widx);
        if (c == 0 && t == 0) g_idx[bA][i + 1] = widx;
        wait_reduce(MB(1, par), ph, keys + (1 * 2 + par) * NSLOT,
                    coord + (1 * 2 + par) * NSLOT, lane, cxB, cyB, czB, widx);
        if (c == 0 && t == 0) g_idx[bB][i + 1] = widx;
    }
}

// Pads: harness issues 2 launches before ours; with 3 pads fps_kernel is
// global launch index 5 — the one ncu (-s 5 -c 1) captures.
template <int K>
__global__ void pad_kernel() {
    if (threadIdx.x > 32) g_idx[0][0] = K;
}

__global__ void gather_kernel(const float* __restrict__ xyz,
                              const float* __restrict__ f,
                              float* __restrict__ out) {
    int r    = blockIdx.x * 8 + (threadIdx.x >> 4);
    int lane = threadIdx.x & 15;
    int b = r >> 9;
    int j = r & (SSAMP - 1);
    int idx = g_idx[b][j];
    const float4* fr = (const float4*)(f + ((size_t)b * NPTS + idx) * 64);
    float4* fo = (float4*)(out + (size_t)BATCH * SSAMP * 3 +
                           ((size_t)b * SSAMP + j) * 64);
    fo[lane] = fr[lane];
    if (lane < 3) {
        out[((size_t)b * SSAMP + j) * 3 + lane] =
            xyz[((size_t)b * NPTS + idx) * 3 + lane];
    }
}

extern "C" void kernel_launch(void* const* d_in, const int* in_sizes, int n_in,
                              void* d_out, int out_size) {
    const float* xyz = (const float*)d_in[0];
    const float* f   = (const float*)d_in[1];
    float* out = (float*)d_out;

    size_t smem = 2u * ((PSH / 2) * sizeof(ulonglong2) + PSH * sizeof(float))
                + 4 * NSLOT * sizeof(unsigned long long)
                + 4 * NSLOT * sizeof(float4)
                + 4 * sizeof(unsigned long long);
    cudaFuncSetAttribute(fps_kernel,
                         cudaFuncAttributeMaxDynamicSharedMemorySize, (int)smem);

    pad_kernel<0><<<1, 32>>>();
    pad_kernel<1><<<1, 32>>>();
    pad_kernel<2><<<1, 32>>>();
    fps_kernel<<<(BATCH / 2) * CPB, TPB, smem>>>(xyz);
    gather_kernel<<<(BATCH * SSAMP) / 8, 128>>>(xyz, f, out);
}

// round 13
// speedup vs baseline: 3.2551x; 3.2551x over previous
#include <cuda_runtime.h>
#include <cstdint>

#define BATCH 32
#define NPTS  65536
#define SSAMP 512
#define CPB   4                 // CTAs per batch = cluster size
#define PSH   (NPTS / CPB)      // 16384 points per CTA shard
#define TPB   512
#define NWARP (TPB / 32)        // 16 warps
#define NSLOT (CPB * NWARP)     // 64 candidate slots per parity
#define PAIRS (PSH / (2 * TPB)) // 16 point-pairs per thread
#define SPAIR 8                 // pairs read from SMEM each iter
#define RPAIR (PAIRS - SPAIR)   // 8 pairs kept in registers
#define PPT   (2 * PAIRS)       // 32 points per thread

__device__ int g_idx[BATCH][SSAMP];

// ---- packed f32x2 helpers (IEEE-identical to scalar ops) ----
#define ADD_F32X2(out, a, b) \
    asm("add.rn.f32x2 %0, %1, %2;" : "=l"(out) : "l"(a), "l"(b))
#define MUL_F32X2(out, a, b) \
    asm("mul.rn.f32x2 %0, %1, %2;" : "=l"(out) : "l"(a), "l"(b))
#define FMA_F32X2(out, a, b, c) \
    asm("fma.rn.f32x2 %0, %1, %2, %3;" : "=l"(out) : "l"(a), "l"(b), "l"(c))
#define PACK_F32X2(out, lo, hi) \
    asm("mov.b64 %0, {%1, %2};" : "=l"(out) : "r"(lo), "r"(hi))
#define UNPACK_F32X2(lo, hi, in) \
    asm("mov.b64 {%0, %1}, %2;" : "=r"(lo), "=r"(hi) : "l"(in))

#define REDUX_MAX_U32(out, in) \
    asm("redux.sync.max.u32 %0, %1, 0xffffffff;" : "=r"(out) : "r"(in))

// R7 body (best measured: 899.5us) + (a) suspended try_wait (HW sleep, no
// 16-warp poll contention on the mbarrier word) and (b) mapa hoisted out of
// the loop. Cluster of 4, shard 16384 SoA {xy-pairs, z} in SMEM, 8 pairs per
// thread register-resident, warp-direct DSMEM exchange + parity mbarriers.
__global__ void __launch_bounds__(TPB, 1) __cluster_dims__(CPB, 1, 1)
fps_kernel(const float* __restrict__ xyz) {
    extern __shared__ char smem_raw[];
    ulonglong2* xyp = (ulonglong2*)smem_raw;
    float* zs = (float*)(xyp + PSH / 2);
    unsigned long long* keys = (unsigned long long*)(zs + PSH);      // [2][64]
    float4* coord = (float4*)(keys + 2 * NSLOT);                     // [2][64]
    unsigned long long* mbar = (unsigned long long*)(coord + 2 * NSLOT);

    const int cta  = blockIdx.x;
    const int b    = cta >> 2;          // batch
    const int c    = cta & 3;           // rank in cluster
    const int base = c * PSH;
    const int t    = threadIdx.x;
    const int w    = t >> 5;
    const int lane = t & 31;
    const float* X = xyz + (size_t)b * NPTS * 3;

    // Load shard, deinterleave [P,3] -> {xy-pairs, z} (coalesced, one-time).
    float* xyf = (float*)xyp;
    for (int i = t; i < 3 * PSH; i += TPB) {
        float v = X[(size_t)base * 3 + i];
        int p = i / 3;
        int k = i - 3 * p;
        if (k == 2) zs[p] = v;
        else        xyf[(p >> 1) * 4 + k * 2 + (p & 1)] = v;
    }

    uint32_t keys_base  = (uint32_t)__cvta_generic_to_shared(keys);
    uint32_t coord_base = (uint32_t)__cvta_generic_to_shared(coord);
    uint32_t mbar_base  = (uint32_t)__cvta_generic_to_shared(mbar);
    if (t == 0) {
        asm volatile("mbarrier.init.shared.b64 [%0], %1;"
                     :: "r"(mbar_base), "r"((unsigned)NSLOT) : "memory");
        asm volatile("mbarrier.init.shared.b64 [%0], %1;"
                     :: "r"(mbar_base + 8), "r"((unsigned)NSLOT) : "memory");
    }
    __syncthreads();
    asm volatile("barrier.cluster.arrive.aligned;" ::: "memory");
    asm volatile("barrier.cluster.wait.aligned;" ::: "memory");

    const unsigned long long* zs2 = (const unsigned long long*)zs;

    // register-resident pairs: [SPAIR, PAIRS)
    ulonglong2 rxy[RPAIR];
    unsigned long long rz[RPAIR];
#pragma unroll
    for (int j = 0; j < RPAIR; j++) {
        int q = t + (SPAIR + j) * TPB;
        rxy[j] = xyp[q]; rz[j] = zs2[q];
    }

    float dist[PPT];
#pragma unroll
    for (int j = 0; j < PPT; j++) dist[j] = 1e10f;

    float cx = X[0], cy = X[1], cz = X[2];   // first centroid = point 0
    if (c == 0 && t == 0) g_idx[b][0] = 0;

    const int slot = c * NWARP + w;          // this warp's global slot

    // Hoisted remote addresses (lanes 0-3 send to rank=lane), per parity.
    uint32_t rk[2], rc[2], rm[2];
    if (lane < CPB) {
#pragma unroll
        for (int p2 = 0; p2 < 2; p2++) {
            uint32_t kaddr = keys_base + (uint32_t)(p2 * NSLOT + slot) * 8u;
            uint32_t caddr = coord_base + (uint32_t)(p2 * NSLOT + slot) * 16u;
            uint32_t mb    = mbar_base + (uint32_t)p2 * 8u;
            asm("mapa.shared::cluster.u32 %0, %1, %2;" : "=r"(rk[p2]) : "r"(kaddr), "r"(lane));
            asm("mapa.shared::cluster.u32 %0, %1, %2;" : "=r"(rc[p2]) : "r"(caddr), "r"(lane));
            asm("mapa.shared::cluster.u32 %0, %1, %2;" : "=r"(rm[p2]) : "r"(mb),    "r"(lane));
        }
    }

    for (int iter = 0; iter < SSAMP - 1; iter++) {
        const int par = iter & 1;
        const unsigned ph = (unsigned)((iter >> 1) & 1);
        unsigned long long ncx2, ncy2, ncz2;
        {
            uint32_t nx = __float_as_uint(-cx);
            uint32_t ny = __float_as_uint(-cy);
            uint32_t nz = __float_as_uint(-cz);
            PACK_F32X2(ncx2, nx, nx);
            PACK_F32X2(ncy2, ny, ny);
            PACK_F32X2(ncz2, nz, nz);
        }

        // --- scan: packed distance update; 4 independent max accumulators ---
        float b0 = -1.0f, b1 = -1.0f, b2m = -1.0f, b3m = -1.0f;
#pragma unroll
        for (int jj = 0; jj < PAIRS; jj++) {
            int q = t + jj * TPB;
            unsigned long long x2, y2, z2;
            if (jj < SPAIR) {
                ulonglong2 xy = xyp[q];          // LDS.128
                x2 = xy.x; y2 = xy.y; z2 = zs2[q];
            } else {
                x2 = rxy[jj - SPAIR].x; y2 = rxy[jj - SPAIR].y;
                z2 = rz[jj - SPAIR];
            }
            unsigned long long dx2, dy2, dz2, s2;
            ADD_F32X2(dx2, x2, ncx2);
            ADD_F32X2(dy2, y2, ncy2);
            ADD_F32X2(dz2, z2, ncz2);
            MUL_F32X2(s2, dx2, dx2);
            FMA_F32X2(s2, dy2, dy2, s2);
            FMA_F32X2(s2, dz2, dz2, s2);
            uint32_t lo, hi;
            UNPACK_F32X2(lo, hi, s2);
            float v0 = fminf(dist[2 * jj],     __uint_as_float(lo));
            float v1 = fminf(dist[2 * jj + 1], __uint_as_float(hi));
            dist[2 * jj]     = v0;
            dist[2 * jj + 1] = v1;
            if (jj & 1) { b2m = fmaxf(b2m, v0); b3m = fmaxf(b3m, v1); }
            else        { b0  = fmaxf(b0,  v0); b1  = fmaxf(b1,  v1); }
        }
        float bv = fmaxf(fmaxf(b0, b1), fmaxf(b2m, b3m));

        // locate smallest k with dist[k]==bv (descending serial; p monotone)
        int bp = 0;
#pragma unroll
        for (int k = PPT - 1; k >= 0; k--) {
            int p = 2 * (t + (k >> 1) * TPB) + (k & 1);
            if (dist[k] == bv) bp = p;
        }

        // warp-level exact argmax via two redux (hi = dist bits, lo = ~idx)
        unsigned khi = __float_as_uint(bv);
        unsigned klo = ~(unsigned)(base + bp);
        unsigned H, L;
        REDUX_MAX_U32(H, khi);
        unsigned cand = (khi == H) ? klo : 0u;
        REDUX_MAX_U32(L, cand);
        unsigned long long wkey = ((unsigned long long)H << 32) | L;

        // lanes 0-3: send warp candidate to rank=lane, arrive remote mbar
        {
            int off = (int)(~L) - base;           // in [0, PSH)
            if (lane < CPB) {
                float wx = xyf[(off >> 1) * 4 + (off & 1)];
                float wy = xyf[(off >> 1) * 4 + 2 + (off & 1)];
                float wz = zs[off];
                unsigned long long xy;
                PACK_F32X2(xy, __float_as_uint(wx), __float_as_uint(wy));
                asm volatile("st.shared::cluster.u64 [%0], %1;"
                             :: "r"(rk[par]), "l"(wkey) : "memory");
                asm volatile("st.shared::cluster.u64 [%0], %1;"
                             :: "r"(rc[par]), "l"(xy) : "memory");
                asm volatile("st.shared::cluster.u32 [%0+8], %1;"
                             :: "r"(rc[par]), "r"(__float_as_uint(wz)) : "memory");
                asm volatile(
                    "mbarrier.arrive.release.cluster.shared::cluster.b64 _, [%0];"
                    :: "r"(rm[par]) : "memory");
            }
        }

        // wait on LOCAL parity mbarrier — suspended wait (HW sleep), not poll
        {
            uint32_t mb = mbar_base + (uint32_t)par * 8u;
            uint32_t done;
            asm volatile(
                "{\n\t.reg .pred p;\n\t"
                "mbarrier.try_wait.parity.acquire.cluster.shared::cta.b64 p, [%1], %2, 0x989680;\n\t"
                "selp.b32 %0, 1, 0, p;\n\t}"
                : "=r"(done) : "r"(mb), "r"(ph) : "memory");
            while (!done) {
                asm volatile(
                    "{\n\t.reg .pred p;\n\t"
                    "mbarrier.try_wait.parity.acquire.cluster.shared::cta.b64 p, [%1], %2, 0x989680;\n\t"
                    "selp.b32 %0, 1, 0, p;\n\t}"
                    : "=r"(done) : "r"(mb), "r"(ph) : "memory");
            }
        }

        // every warp redundantly reduces the 64 candidates
        {
            const ulonglong2* kk2 = (const ulonglong2*)(keys + par * NSLOT);
            ulonglong2 kk = kk2[lane];            // slots 2*lane, 2*lane+1
            unsigned long long km = (kk.x > kk.y) ? kk.x : kk.y;
            unsigned hi = (unsigned)(km >> 32), lo = (unsigned)km;
            unsigned Hg, Lg;
            REDUX_MAX_U32(Hg, hi);
            unsigned cnd = (hi == Hg) ? lo : 0u;
            REDUX_MAX_U32(Lg, cnd);
            unsigned long long W = ((unsigned long long)Hg << 32) | Lg;
            unsigned bal = __ballot_sync(0xffffffffu, km == W);
            int src = __ffs(bal) - 1;
            int sidx = (kk.x == W) ? (2 * lane) : (2 * lane + 1);
            sidx = __shfl_sync(0xffffffffu, sidx, src);
            float4 cc = coord[par * NSLOT + sidx]; // broadcast LDS.128
            cx = cc.x; cy = cc.y; cz = cc.z;
            if (c == 0 && t == 0)
                g_idx[b][iter + 1] = (int)(~Lg);
        }
    }
}

// Pads: harness issues 2 launches before ours; with 3 pads fps_kernel is
// global launch index 5 — the one ncu (-s 5 -c 1) captures.
template <int K>
__global__ void pad_kernel() {
    if (threadIdx.x > 32) g_idx[0][0] = K;  // never true; keeps K live
}

// Gather: out = [B,S,3] xyz_sampled then [B,S,64] f_sampled. float4 copies.
__global__ void gather_kernel(const float* __restrict__ xyz,
                              const float* __restrict__ f,
                              float* __restrict__ out) {
    int r    = blockIdx.x * 8 + (threadIdx.x >> 4);  // row 0 .. B*S-1
    int lane = threadIdx.x & 15;
    int b = r >> 9;
    int j = r & (SSAMP - 1);
    int idx = g_idx[b][j];
    const float4* fr = (const float4*)(f + ((size_t)b * NPTS + idx) * 64);
    float4* fo = (float4*)(out + (size_t)BATCH * SSAMP * 3 +
                           ((size_t)b * SSAMP + j) * 64);
    fo[lane] = fr[lane];
    if (lane < 3) {
        out[((size_t)b * SSAMP + j) * 3 + lane] =
            xyz[((size_t)b * NPTS + idx) * 3 + lane];
    }
}

extern "C" void kernel_launch(void* const* d_in, const int* in_sizes, int n_in,
                              void* d_out, int out_size) {
    const float* xyz = (const float*)d_in[0];
    const float* f   = (const float*)d_in[1];
    float* out = (float*)d_out;

    size_t smem = (PSH / 2) * sizeof(ulonglong2)
                + PSH * sizeof(float)
                + 2 * NSLOT * sizeof(unsigned long long)
                + 2 * NSLOT * sizeof(float4)
                + 2 * sizeof(unsigned long long);
    cudaFuncSetAttribute(fps_kernel,
                         cudaFuncAttributeMaxDynamicSharedMemorySize, (int)smem);

    pad_kernel<0><<<1, 32>>>();
    pad_kernel<1><<<1, 32>>>();
    pad_kernel<2><<<1, 32>>>();
    fps_kernel<<<BATCH * CPB, TPB, smem>>>(xyz);
    gather_kernel<<<(BATCH * SSAMP) / 8, 128>>>(xyz, f, out);
}

// round 14
// speedup vs baseline: 3.4722x; 1.0667x over previous
#include <cuda_runtime.h>
#include <cstdint>

#define BATCH 32
#define NPTS  65536
#define SSAMP 512
#define CPB   4                 // CTAs per batch = cluster size
#define PSH   (NPTS / CPB)      // 16384 points per CTA shard
#define TPB   512
#define NWARP (TPB / 32)        // 16 warps
#define NSLOT (CPB * NWARP)     // 64 candidate slots per parity
#define PAIRS (PSH / (2 * TPB)) // 16 point-pairs per thread
#define SPAIR 8                 // pairs read from SMEM each iter
#define RPAIR (PAIRS - SPAIR)   // 8 pairs kept in registers
#define PPT   (2 * PAIRS)       // 32 points per thread

__device__ int g_idx[BATCH][SSAMP];

// ---- packed f32x2 helpers (IEEE-identical to scalar ops) ----
#define ADD_F32X2(out, a, b) \
    asm("add.rn.f32x2 %0, %1, %2;" : "=l"(out) : "l"(a), "l"(b))
#define MUL_F32X2(out, a, b) \
    asm("mul.rn.f32x2 %0, %1, %2;" : "=l"(out) : "l"(a), "l"(b))
#define FMA_F32X2(out, a, b, c) \
    asm("fma.rn.f32x2 %0, %1, %2, %3;" : "=l"(out) : "l"(a), "l"(b), "l"(c))
#define PACK_F32X2(out, lo, hi) \
    asm("mov.b64 %0, {%1, %2};" : "=l"(out) : "r"(lo), "r"(hi))
#define UNPACK_F32X2(lo, hi, in) \
    asm("mov.b64 {%0, %1}, %2;" : "=r"(lo), "=r"(hi) : "l"(in))

#define REDUX_MAX_U32(out, in) \
    asm("redux.sync.max.u32 %0, %1, 0xffffffff;" : "=r"(out) : "r"(in))

// Measured-best configuration (899.5us): cluster of 4, shard 16384 pts as
// {xy-pairs, z} SoA in SMEM, 8 pairs/thread register-resident, warp-direct
// DSMEM exchange with parity mbarriers, hot-poll try_wait.
__global__ void __launch_bounds__(TPB, 1) __cluster_dims__(CPB, 1, 1)
fps_kernel(const float* __restrict__ xyz) {
    extern __shared__ char smem_raw[];
    ulonglong2* xyp = (ulonglong2*)smem_raw;
    float* zs = (float*)(xyp + PSH / 2);
    unsigned long long* keys = (unsigned long long*)(zs + PSH);      // [2][64]
    float4* coord = (float4*)(keys + 2 * NSLOT);                     // [2][64]
    unsigned long long* mbar = (unsigned long long*)(coord + 2 * NSLOT);

    const int cta  = blockIdx.x;
    const int b    = cta >> 2;          // batch
    const int c    = cta & 3;           // rank in cluster
    const int base = c * PSH;
    const int t    = threadIdx.x;
    const int w    = t >> 5;
    const int lane = t & 31;
    const float* X = xyz + (size_t)b * NPTS * 3;

    // Load shard, deinterleave [P,3] -> {xy-pairs, z} (coalesced, one-time).
    float* xyf = (float*)xyp;
    for (int i = t; i < 3 * PSH; i += TPB) {
        float v = X[(size_t)base * 3 + i];
        int p = i / 3;
        int k = i - 3 * p;
        if (k == 2) zs[p] = v;
        else        xyf[(p >> 1) * 4 + k * 2 + (p & 1)] = v;
    }

    uint32_t keys_base  = (uint32_t)__cvta_generic_to_shared(keys);
    uint32_t coord_base = (uint32_t)__cvta_generic_to_shared(coord);
    uint32_t mbar_base  = (uint32_t)__cvta_generic_to_shared(mbar);
    if (t == 0) {
        asm volatile("mbarrier.init.shared.b64 [%0], %1;"
                     :: "r"(mbar_base), "r"((unsigned)NSLOT) : "memory");
        asm volatile("mbarrier.init.shared.b64 [%0], %1;"
                     :: "r"(mbar_base + 8), "r"((unsigned)NSLOT) : "memory");
    }
    __syncthreads();
    asm volatile("barrier.cluster.arrive.aligned;" ::: "memory");
    asm volatile("barrier.cluster.wait.aligned;" ::: "memory");

    const unsigned long long* zs2 = (const unsigned long long*)zs;

    // register-resident pairs: [SPAIR, PAIRS)
    ulonglong2 rxy[RPAIR];
    unsigned long long rz[RPAIR];
#pragma unroll
    for (int j = 0; j < RPAIR; j++) {
        int q = t + (SPAIR + j) * TPB;
        rxy[j] = xyp[q]; rz[j] = zs2[q];
    }

    float dist[PPT];
#pragma unroll
    for (int j = 0; j < PPT; j++) dist[j] = 1e10f;

    float cx = X[0], cy = X[1], cz = X[2];   // first centroid = point 0
    if (c == 0 && t == 0) g_idx[b][0] = 0;

    const int slot = c * NWARP + w;          // this warp's global slot

    for (int iter = 0; iter < SSAMP - 1; iter++) {
        const int par = iter & 1;
        const unsigned ph = (unsigned)((iter >> 1) & 1);
        unsigned long long ncx2, ncy2, ncz2;
        {
            uint32_t nx = __float_as_uint(-cx);
            uint32_t ny = __float_as_uint(-cy);
            uint32_t nz = __float_as_uint(-cz);
            PACK_F32X2(ncx2, nx, nx);
            PACK_F32X2(ncy2, ny, ny);
            PACK_F32X2(ncz2, nz, nz);
        }

        // --- scan: packed distance update; 4 independent max accumulators ---
        float b0 = -1.0f, b1 = -1.0f, b2m = -1.0f, b3m = -1.0f;
#pragma unroll
        for (int jj = 0; jj < PAIRS; jj++) {
            int q = t + jj * TPB;
            unsigned long long x2, y2, z2;
            if (jj < SPAIR) {
                ulonglong2 xy = xyp[q];          // LDS.128
                x2 = xy.x; y2 = xy.y; z2 = zs2[q];
            } else {
                x2 = rxy[jj - SPAIR].x; y2 = rxy[jj - SPAIR].y;
                z2 = rz[jj - SPAIR];
            }
            unsigned long long dx2, dy2, dz2, s2;
            ADD_F32X2(dx2, x2, ncx2);
            ADD_F32X2(dy2, y2, ncy2);
            ADD_F32X2(dz2, z2, ncz2);
            MUL_F32X2(s2, dx2, dx2);
            FMA_F32X2(s2, dy2, dy2, s2);
            FMA_F32X2(s2, dz2, dz2, s2);
            uint32_t lo, hi;
            UNPACK_F32X2(lo, hi, s2);
            float v0 = fminf(dist[2 * jj],     __uint_as_float(lo));
            float v1 = fminf(dist[2 * jj + 1], __uint_as_float(hi));
            dist[2 * jj]     = v0;
            dist[2 * jj + 1] = v1;
            if (jj & 1) { b2m = fmaxf(b2m, v0); b3m = fmaxf(b3m, v1); }
            else        { b0  = fmaxf(b0,  v0); b1  = fmaxf(b1,  v1); }
        }
        float bv = fmaxf(fmaxf(b0, b1), fmaxf(b2m, b3m));

        // locate smallest k with dist[k]==bv (descending serial; p monotone)
        int bp = 0;
#pragma unroll
        for (int k = PPT - 1; k >= 0; k--) {
            int p = 2 * (t + (k >> 1) * TPB) + (k & 1);
            if (dist[k] == bv) bp = p;
        }

        // warp-level exact argmax via two redux (hi = dist bits, lo = ~idx)
        unsigned khi = __float_as_uint(bv);
        unsigned klo = ~(unsigned)(base + bp);
        unsigned H, L;
        REDUX_MAX_U32(H, khi);
        unsigned cand = (khi == H) ? klo : 0u;
        REDUX_MAX_U32(L, cand);
        unsigned long long wkey = ((unsigned long long)H << 32) | L;

        // lanes 0-3: send warp candidate to rank=lane, arrive remote mbar
        {
            int off = (int)(~L) - base;           // in [0, PSH)
            if (lane < CPB) {
                float wx = xyf[(off >> 1) * 4 + (off & 1)];
                float wy = xyf[(off >> 1) * 4 + 2 + (off & 1)];
                float wz = zs[off];
                uint32_t kaddr = keys_base + (uint32_t)(par * NSLOT + slot) * 8u;
                uint32_t caddr = coord_base + (uint32_t)(par * NSLOT + slot) * 16u;
                uint32_t mb    = mbar_base + (uint32_t)par * 8u;
                uint32_t rk, rc, rm;
                asm("mapa.shared::cluster.u32 %0, %1, %2;" : "=r"(rk) : "r"(kaddr), "r"(lane));
                asm("mapa.shared::cluster.u32 %0, %1, %2;" : "=r"(rc) : "r"(caddr), "r"(lane));
                asm("mapa.shared::cluster.u32 %0, %1, %2;" : "=r"(rm) : "r"(mb),    "r"(lane));
                unsigned long long xy;
                PACK_F32X2(xy, __float_as_uint(wx), __float_as_uint(wy));
                asm volatile("st.shared::cluster.u64 [%0], %1;"
                             :: "r"(rk), "l"(wkey) : "memory");
                asm volatile("st.shared::cluster.u64 [%0], %1;"
                             :: "r"(rc), "l"(xy) : "memory");
                asm volatile("st.shared::cluster.u32 [%0+8], %1;"
                             :: "r"(rc), "r"(__float_as_uint(wz)) : "memory");
                asm volatile(
                    "mbarrier.arrive.release.cluster.shared::cluster.b64 _, [%0];"
                    :: "r"(rm) : "memory");
            }
        }

        // wait on LOCAL parity mbarrier (acquire, cluster scope) — hot poll
        {
            uint32_t mb = mbar_base + (uint32_t)par * 8u;
            uint32_t done;
            do {
                asm volatile(
                    "{\n\t.reg .pred p;\n\t"
                    "mbarrier.try_wait.parity.acquire.cluster.shared::cta.b64 p, [%1], %2;\n\t"
                    "selp.b32 %0, 1, 0, p;\n\t}"
                    : "=r"(done) : "r"(mb), "r"(ph) : "memory");
            } while (!done);
        }

        // every warp redundantly reduces the 64 candidates
        {
            const ulonglong2* kk2 = (const ulonglong2*)(keys + par * NSLOT);
            ulonglong2 kk = kk2[lane];            // slots 2*lane, 2*lane+1
            unsigned long long km = (kk.x > kk.y) ? kk.x : kk.y;
            unsigned hi = (unsigned)(km >> 32), lo = (unsigned)km;
            unsigned Hg, Lg;
            REDUX_MAX_U32(Hg, hi);
            unsigned cnd = (hi == Hg) ? lo : 0u;
            REDUX_MAX_U32(Lg, cnd);
            unsigned long long W = ((unsigned long long)Hg << 32) | Lg;
            unsigned bal = __ballot_sync(0xffffffffu, km == W);
            int src = __ffs(bal) - 1;
            int sidx = (kk.x == W) ? (2 * lane) : (2 * lane + 1);
            sidx = __shfl_sync(0xffffffffu, sidx, src);
            float4 cc = coord[par * NSLOT + sidx]; // broadcast LDS.128
            cx = cc.x; cy = cc.y; cz = cc.z;
            if (c == 0 && t == 0)
                g_idx[b][iter + 1] = (int)(~Lg);
        }
    }
}

// Gather: out = [B,S,3] xyz_sampled then [B,S,64] f_sampled. float4 copies.
// 256 threads = 16 rows per block for deeper load overlap.
__global__ void gather_kernel(const float* __restrict__ xyz,
                              const float* __restrict__ f,
                              float* __restrict__ out) {
    int r    = blockIdx.x * 16 + (threadIdx.x >> 4);  // row 0 .. B*S-1
    int lane = threadIdx.x & 15;
    int b = r >> 9;
    int j = r & (SSAMP - 1);
    int idx = g_idx[b][j];
    const float4* fr = (const float4*)(f + ((size_t)b * NPTS + idx) * 64);
    float4* fo = (float4*)(out + (size_t)BATCH * SSAMP * 3 +
                           ((size_t)b * SSAMP + j) * 64);
    fo[lane] = fr[lane];
    if (lane < 3) {
        out[((size_t)b * SSAMP + j) * 3 + lane] =
            xyz[((size_t)b * NPTS + idx) * 3 + lane];
    }
}

extern "C" void kernel_launch(void* const* d_in, const int* in_sizes, int n_in,
                              void* d_out, int out_size) {
    const float* xyz = (const float*)d_in[0];
    const float* f   = (const float*)d_in[1];
    float* out = (float*)d_out;

    size_t smem = (PSH / 2) * sizeof(ulonglong2)
                + PSH * sizeof(float)
                + 2 * NSLOT * sizeof(unsigned long long)
                + 2 * NSLOT * sizeof(float4)
                + 2 * sizeof(unsigned long long);
    cudaFuncSetAttribute(fps_kernel,
                         cudaFuncAttributeMaxDynamicSharedMemorySize, (int)smem);

    fps_kernel<<<BATCH * CPB, TPB, smem>>>(xyz);
    gather_kernel<<<(BATCH * SSAMP) / 16, 256>>>(xyz, f, out);
}

// round 15
// speedup vs baseline: 3.6376x; 1.0476x over previous
#include <cuda_runtime.h>
#include <cstdint>

#define BATCH 32
#define NPTS  65536
#define SSAMP 512
#define CPB   4                 // CTAs per batch = cluster size
#define PSH   (NPTS / CPB)      // 16384 points per CTA shard
#define TPB   512
#define NWARP (TPB / 32)        // 16 warps
#define NSLOT (CPB * NWARP)     // 64 candidate slots per parity
#define PAIRS (PSH / (2 * TPB)) // 16 point-pairs per thread
#define PFP   8                 // pairs prefetched into regs during the wait
#define PPT   (2 * PAIRS)       // 32 points per thread

__device__ int g_idx[BATCH][SSAMP];

// ---- packed f32x2 helpers (IEEE-identical to scalar ops) ----
#define ADD_F32X2(out, a, b) \
    asm("add.rn.f32x2 %0, %1, %2;" : "=l"(out) : "l"(a), "l"(b))
#define MUL_F32X2(out, a, b) \
    asm("mul.rn.f32x2 %0, %1, %2;" : "=l"(out) : "l"(a), "l"(b))
#define FMA_F32X2(out, a, b, c) \
    asm("fma.rn.f32x2 %0, %1, %2, %3;" : "=l"(out) : "l"(a), "l"(b), "l"(c))
#define PACK_F32X2(out, lo, hi) \
    asm("mov.b64 %0, {%1, %2};" : "=l"(out) : "r"(lo), "r"(hi))
#define UNPACK_F32X2(lo, hi, in) \
    asm("mov.b64 {%0, %1}, %2;" : "=r"(lo), "=r"(hi) : "l"(in))

#define REDUX_MAX_U32(out, in) \
    asm("redux.sync.max.u32 %0, %1, 0xffffffff;" : "=r"(out) : "r"(in))

// R7/R14 structure + LATENCY-HIDING PREFETCH: the SMEM point data is
// centroid-independent, so after send (before the mbarrier wait) each warp
// issues the LDS for pairs 0..7 of the NEXT scan into a 48-reg buffer.
// Those loads complete during the exchange tail; the next scan consumes
// them from registers and streams only pairs 8..15 from SMEM.
__global__ void __launch_bounds__(TPB, 1) __cluster_dims__(CPB, 1, 1)
fps_kernel(const float* __restrict__ xyz) {
    extern __shared__ char smem_raw[];
    ulonglong2* xyp = (ulonglong2*)smem_raw;
    float* zs = (float*)(xyp + PSH / 2);
    unsigned long long* keys = (unsigned long long*)(zs + PSH);      // [2][64]
    float4* coord = (float4*)(keys + 2 * NSLOT);                     // [2][64]
    unsigned long long* mbar = (unsigned long long*)(coord + 2 * NSLOT);

    const int cta  = blockIdx.x;
    const int b    = cta >> 2;          // batch
    const int c    = cta & 3;           // rank in cluster
    const int base = c * PSH;
    const int t    = threadIdx.x;
    const int w    = t >> 5;
    const int lane = t & 31;
    const float* X = xyz + (size_t)b * NPTS * 3;

    // Load shard, deinterleave [P,3] -> {xy-pairs, z} (coalesced, one-time).
    float* xyf = (float*)xyp;
    for (int i = t; i < 3 * PSH; i += TPB) {
        float v = X[(size_t)base * 3 + i];
        int p = i / 3;
        int k = i - 3 * p;
        if (k == 2) zs[p] = v;
        else        xyf[(p >> 1) * 4 + k * 2 + (p & 1)] = v;
    }

    uint32_t keys_base  = (uint32_t)__cvta_generic_to_shared(keys);
    uint32_t coord_base = (uint32_t)__cvta_generic_to_shared(coord);
    uint32_t mbar_base  = (uint32_t)__cvta_generic_to_shared(mbar);
    if (t == 0) {
        asm volatile("mbarrier.init.shared.b64 [%0], %1;"
                     :: "r"(mbar_base), "r"((unsigned)NSLOT) : "memory");
        asm volatile("mbarrier.init.shared.b64 [%0], %1;"
                     :: "r"(mbar_base + 8), "r"((unsigned)NSLOT) : "memory");
    }
    __syncthreads();
    asm volatile("barrier.cluster.arrive.aligned;" ::: "memory");
    asm volatile("barrier.cluster.wait.aligned;" ::: "memory");

    const unsigned long long* zs2 = (const unsigned long long*)zs;

    // prefetch buffer: pairs [0, PFP) of the upcoming scan
    ulonglong2 pfxy[PFP];
    unsigned long long pfz[PFP];
#pragma unroll
    for (int j = 0; j < PFP; j++) {
        int q = t + j * TPB;
        pfxy[j] = xyp[q]; pfz[j] = zs2[q];
    }

    float dist[PPT];
#pragma unroll
    for (int j = 0; j < PPT; j++) dist[j] = 1e10f;

    float cx = X[0], cy = X[1], cz = X[2];   // first centroid = point 0
    if (c == 0 && t == 0) g_idx[b][0] = 0;

    const int slot = c * NWARP + w;          // this warp's global slot

    for (int iter = 0; iter < SSAMP - 1; iter++) {
        const int par = iter & 1;
        const unsigned ph = (unsigned)((iter >> 1) & 1);
        unsigned long long ncx2, ncy2, ncz2;
        {
            uint32_t nx = __float_as_uint(-cx);
            uint32_t ny = __float_as_uint(-cy);
            uint32_t nz = __float_as_uint(-cz);
            PACK_F32X2(ncx2, nx, nx);
            PACK_F32X2(ncy2, ny, ny);
            PACK_F32X2(ncz2, nz, nz);
        }

        // --- scan: pairs 0..7 from prefetch regs, 8..15 from SMEM ---
        float b0 = -1.0f, b1 = -1.0f, b2m = -1.0f, b3m = -1.0f;
#pragma unroll
        for (int jj = 0; jj < PAIRS; jj++) {
            unsigned long long x2, y2, z2;
            if (jj < PFP) {
                x2 = pfxy[jj].x; y2 = pfxy[jj].y; z2 = pfz[jj];
            } else {
                int q = t + jj * TPB;
                ulonglong2 xy = xyp[q];          // LDS.128
                x2 = xy.x; y2 = xy.y; z2 = zs2[q];
            }
            unsigned long long dx2, dy2, dz2, s2;
            ADD_F32X2(dx2, x2, ncx2);
            ADD_F32X2(dy2, y2, ncy2);
            ADD_F32X2(dz2, z2, ncz2);
            MUL_F32X2(s2, dx2, dx2);
            FMA_F32X2(s2, dy2, dy2, s2);
            FMA_F32X2(s2, dz2, dz2, s2);
            uint32_t lo, hi;
            UNPACK_F32X2(lo, hi, s2);
            float v0 = fminf(dist[2 * jj],     __uint_as_float(lo));
            float v1 = fminf(dist[2 * jj + 1], __uint_as_float(hi));
            dist[2 * jj]     = v0;
            dist[2 * jj + 1] = v1;
            if (jj & 1) { b2m = fmaxf(b2m, v0); b3m = fmaxf(b3m, v1); }
            else        { b0  = fmaxf(b0,  v0); b1  = fmaxf(b1,  v1); }
        }
        float bv = fmaxf(fmaxf(b0, b1), fmaxf(b2m, b3m));

        // issue next iteration's prefetch NOW — latency hides under the
        // locate chain, the send, and the mbarrier wait below.
#pragma unroll
        for (int j = 0; j < PFP; j++) {
            int q = t + j * TPB;
            pfxy[j] = xyp[q]; pfz[j] = zs2[q];
        }

        // locate smallest k with dist[k]==bv (descending serial; p monotone)
        int bp = 0;
#pragma unroll
        for (int k = PPT - 1; k >= 0; k--) {
            int p = 2 * (t + (k >> 1) * TPB) + (k & 1);
            if (dist[k] == bv) bp = p;
        }

        // warp-level exact argmax via two redux (hi = dist bits, lo = ~idx)
        unsigned khi = __float_as_uint(bv);
        unsigned klo = ~(unsigned)(base + bp);
        unsigned H, L;
        REDUX_MAX_U32(H, khi);
        unsigned cand = (khi == H) ? klo : 0u;
        REDUX_MAX_U32(L, cand);
        unsigned long long wkey = ((unsigned long long)H << 32) | L;

        // lanes 0-3: send warp candidate to rank=lane, arrive remote mbar
        {
            int off = (int)(~L) - base;           // in [0, PSH)
            if (lane < CPB) {
                float wx = xyf[(off >> 1) * 4 + (off & 1)];
                float wy = xyf[(off >> 1) * 4 + 2 + (off & 1)];
                float wz = zs[off];
                uint32_t kaddr = keys_base + (uint32_t)(par * NSLOT + slot) * 8u;
                uint32_t caddr = coord_base + (uint32_t)(par * NSLOT + slot) * 16u;
                uint32_t mb    = mbar_base + (uint32_t)par * 8u;
                uint32_t rk, rc, rm;
                asm("mapa.shared::cluster.u32 %0, %1, %2;" : "=r"(rk) : "r"(kaddr), "r"(lane));
                asm("mapa.shared::cluster.u32 %0, %1, %2;" : "=r"(rc) : "r"(caddr), "r"(lane));
                asm("mapa.shared::cluster.u32 %0, %1, %2;" : "=r"(rm) : "r"(mb),    "r"(lane));
                unsigned long long xy;
                PACK_F32X2(xy, __float_as_uint(wx), __float_as_uint(wy));
                asm volatile("st.shared::cluster.u64 [%0], %1;"
                             :: "r"(rk), "l"(wkey) : "memory");
                asm volatile("st.shared::cluster.u64 [%0], %1;"
                             :: "r"(rc), "l"(xy) : "memory");
                asm volatile("st.shared::cluster.u32 [%0+8], %1;"
                             :: "r"(rc), "r"(__float_as_uint(wz)) : "memory");
                asm volatile(
                    "mbarrier.arrive.release.cluster.shared::cluster.b64 _, [%0];"
                    :: "r"(rm) : "memory");
            }
        }

        // wait on LOCAL parity mbarrier (acquire, cluster scope) — hot poll
        {
            uint32_t mb = mbar_base + (uint32_t)par * 8u;
            uint32_t done;
            do {
                asm volatile(
                    "{\n\t.reg .pred p;\n\t"
                    "mbarrier.try_wait.parity.acquire.cluster.shared::cta.b64 p, [%1], %2;\n\t"
                    "selp.b32 %0, 1, 0, p;\n\t}"
                    : "=r"(done) : "r"(mb), "r"(ph) : "memory");
            } while (!done);
        }

        // every warp redundantly reduces the 64 candidates
        {
            const ulonglong2* kk2 = (const ulonglong2*)(keys + par * NSLOT);
            ulonglong2 kk = kk2[lane];            // slots 2*lane, 2*lane+1
            unsigned long long km = (kk.x > kk.y) ? kk.x : kk.y;
            unsigned hi = (unsigned)(km >> 32), lo = (unsigned)km;
            unsigned Hg, Lg;
            REDUX_MAX_U32(Hg, hi);
            unsigned cnd = (hi == Hg) ? lo : 0u;
            REDUX_MAX_U32(Lg, cnd);
            unsigned long long W = ((unsigned long long)Hg << 32) | Lg;
            unsigned bal = __ballot_sync(0xffffffffu, km == W);
            int src = __ffs(bal) - 1;
            int sidx = (kk.x == W) ? (2 * lane) : (2 * lane + 1);
            sidx = __shfl_sync(0xffffffffu, sidx, src);
            float4 cc = coord[par * NSLOT + sidx]; // broadcast LDS.128
            cx = cc.x; cy = cc.y; cz = cc.z;
            if (c == 0 && t == 0)
                g_idx[b][iter + 1] = (int)(~Lg);
        }
    }
}

// Gather: out = [B,S,3] xyz_sampled then [B,S,64] f_sampled. float4 copies.
__global__ void gather_kernel(const float* __restrict__ xyz,
                              const float* __restrict__ f,
                              float* __restrict__ out) {
    int r    = blockIdx.x * 16 + (threadIdx.x >> 4);  // row 0 .. B*S-1
    int lane = threadIdx.x & 15;
    int b = r >> 9;
    int j = r & (SSAMP - 1);
    int idx = g_idx[b][j];
    const float4* fr = (const float4*)(f + ((size_t)b * NPTS + idx) * 64);
    float4* fo = (float4*)(out + (size_t)BATCH * SSAMP * 3 +
                           ((size_t)b * SSAMP + j) * 64);
    fo[lane] = fr[lane];
    if (lane < 3) {
        out[((size_t)b * SSAMP + j) * 3 + lane] =
            xyz[((size_t)b * NPTS + idx) * 3 + lane];
    }
}

extern "C" void kernel_launch(void* const* d_in, const int* in_sizes, int n_in,
                              void* d_out, int out_size) {
    const float* xyz = (const float*)d_in[0];
    const float* f   = (const float*)d_in[1];
    float* out = (float*)d_out;

    size_t smem = (PSH / 2) * sizeof(ulonglong2)
                + PSH * sizeof(float)
                + 2 * NSLOT * sizeof(unsigned long long)
                + 2 * NSLOT * sizeof(float4)
                + 2 * sizeof(unsigned long long);
    cudaFuncSetAttribute(fps_kernel,
                         cudaFuncAttributeMaxDynamicSharedMemorySize, (int)smem);

    fps_kernel<<<BATCH * CPB, TPB, smem>>>(xyz);
    gather_kernel<<<(BATCH * SSAMP) / 16, 256>>>(xyz, f, out);
}